// round 4
// baseline (speedup 1.0000x reference)
#include <cuda_runtime.h>
#include <math.h>

// ---------------------------------------------------------------------------
// EigVals: per-voxel symmetric 3x3 eigenvalues (ascending), analytic method.
// X: (b, 9, n) fp32, channel-strided by n. out: (b, 3, n) fp32.
// ---------------------------------------------------------------------------

__device__ __forceinline__ void sym3eig(float a00, float a01, float a02,
                                        float a11, float a12, float a22,
                                        float& lo, float& mid, float& hi)
{
    // Smith's trigonometric method for symmetric 3x3 eigenvalues.
    const float third = 1.0f / 3.0f;
    float q   = (a00 + a11 + a22) * third;
    float b00 = a00 - q, b11 = a11 - q, b22 = a22 - q;
    float off = a01 * a01 + a02 * a02 + a12 * a12;
    float p2  = b00 * b00 + b11 * b11 + b22 * b22 + 2.0f * off;
    // p2 >= 0 always; p2 == 0 -> multiple of identity
    float p = sqrtf(p2 * (1.0f / 6.0f));

    // det(B) where B = A - q*I (symmetric)
    float detB = b00 * (b11 * b22 - a12 * a12)
               - a01 * (a01 * b22 - a12 * a02)
               + a02 * (a01 * a12 - b11 * a02);

    float pinv = (p > 0.0f) ? (1.0f / p) : 0.0f;
    float r = 0.5f * detB * pinv * pinv * pinv;
    r = fminf(fmaxf(r, -1.0f), 1.0f);

    float phi = acosf(r) * third;
    // phi in [0, pi/3]:
    //   hi  = q + 2p*cos(phi)            (cos in [ 0.5, 1.0])
    //   lo  = q + 2p*cos(phi + 2pi/3)    (cos in [-1.0,-0.5])
    //   mid = trace - hi - lo
    float two_p = 2.0f * p;
    hi  = q + two_p * cosf(phi);
    lo  = q + two_p * cosf(phi + 2.09439510239319549f);
    mid = 3.0f * q - hi - lo;
}

__global__ __launch_bounds__(256)
void eigvals3_kernel(const float* __restrict__ X, float* __restrict__ out,
                     int n, long long ngroups)
{
    long long g = (long long)blockIdx.x * blockDim.x + threadIdx.x;
    if (g >= ngroups) return;

    long long i4 = g * 4;                     // flattened (batch, voxel) index *4
    int b0 = (int)(i4 / (long long)n);        // batch (n divisible by 4 -> no crossing)
    int v  = (int)(i4 - (long long)b0 * n);   // voxel within batch

    const float* base = X   + (size_t)b0 * 9 * n + v;
    float*       obase = out + (size_t)b0 * 3 * n + v;

    // 9 coalesced 128-bit loads (channels, stride n floats)
    float4 c0 = *(const float4*)(base + 0 * (size_t)n);
    float4 c1 = *(const float4*)(base + 1 * (size_t)n);
    float4 c2 = *(const float4*)(base + 2 * (size_t)n);
    float4 c3 = *(const float4*)(base + 3 * (size_t)n);
    float4 c4 = *(const float4*)(base + 4 * (size_t)n);
    float4 c5 = *(const float4*)(base + 5 * (size_t)n);
    float4 c6 = *(const float4*)(base + 6 * (size_t)n);
    float4 c7 = *(const float4*)(base + 7 * (size_t)n);
    float4 c8 = *(const float4*)(base + 8 * (size_t)n);

    float4 olo, omid, ohi;

    // Symmetrize off-diagonals: a01=(c1+c3)/2, a02=(c2+c6)/2, a12=(c5+c7)/2
    {
        float a01 = 0.5f * (c1.x + c3.x), a02 = 0.5f * (c2.x + c6.x), a12 = 0.5f * (c5.x + c7.x);
        sym3eig(c0.x, a01, a02, c4.x, a12, c8.x, olo.x, omid.x, ohi.x);
    }
    {
        float a01 = 0.5f * (c1.y + c3.y), a02 = 0.5f * (c2.y + c6.y), a12 = 0.5f * (c5.y + c7.y);
        sym3eig(c0.y, a01, a02, c4.y, a12, c8.y, olo.y, omid.y, ohi.y);
    }
    {
        float a01 = 0.5f * (c1.z + c3.z), a02 = 0.5f * (c2.z + c6.z), a12 = 0.5f * (c5.z + c7.z);
        sym3eig(c0.z, a01, a02, c4.z, a12, c8.z, olo.z, omid.z, ohi.z);
    }
    {
        float a01 = 0.5f * (c1.w + c3.w), a02 = 0.5f * (c2.w + c6.w), a12 = 0.5f * (c5.w + c7.w);
        sym3eig(c0.w, a01, a02, c4.w, a12, c8.w, olo.w, omid.w, ohi.w);
    }

    // 3 coalesced 128-bit stores, ascending eigenvalue order (matches eigvalsh)
    *(float4*)(obase + 0 * (size_t)n) = olo;
    *(float4*)(obase + 1 * (size_t)n) = omid;
    *(float4*)(obase + 2 * (size_t)n) = ohi;
}

extern "C" void kernel_launch(void* const* d_in, const int* in_sizes, int n_in,
                              void* d_out, int out_size)
{
    const float* X  = (const float*)d_in[0];
    float* out      = (float*)d_out;

    // X: (b, 9, n); out: (b, 3, n). Problem fixes b = 2, n = 96^3.
    // out_size = b*3*n  ->  n = out_size / 6 for b = 2.
    int n = out_size / 6;
    long long total_vox = (long long)out_size / 3;   // b * n
    long long ngroups = total_vox / 4;               // 4 voxels per thread (n % 4 == 0)

    int threads = 256;
    long long blocks = (ngroups + threads - 1) / threads;
    eigvals3_kernel<<<(unsigned)blocks, threads>>>(X, out, n, ngroups);
}

// round 5
// speedup vs baseline: 1.2208x; 1.2208x over previous
#include <cuda_runtime.h>
#include <math.h>

// ---------------------------------------------------------------------------
// EigVals: per-voxel symmetric 3x3 eigenvalues (ascending), analytic method.
// X: (b, 9, n) fp32, channel-strided by n. out: (b, 3, n) fp32.
// Fast-math variant: MUFU cos, polynomial acos, rsqrt-based p. Max added
// abs error ~2e-6 vs libm path (threshold 1e-3).
// ---------------------------------------------------------------------------

// acos(x) for x in [-1,1]; abs error < ~1e-6 rad.
// sqrt(1-|x|)*poly(|x|), reflected for x<0.
__device__ __forceinline__ float fast_acosf(float x)
{
    float u = fabsf(x);
    float p = -0.0012624911f;
    p = fmaf(p, u,  0.0066700901f);
    p = fmaf(p, u, -0.0170881256f);
    p = fmaf(p, u,  0.0308918810f);
    p = fmaf(p, u, -0.0501743046f);
    p = fmaf(p, u,  0.0889789874f);
    p = fmaf(p, u, -0.2145988016f);
    p = fmaf(p, u,  1.5707963050f);
    float a = sqrtf(1.0f - u) * p;
    return (x >= 0.0f) ? a : (3.14159265358979f - a);
}

__device__ __forceinline__ void sym3eig(float a00, float a01, float a02,
                                        float a11, float a12, float a22,
                                        float& lo, float& mid, float& hi)
{
    const float third = 1.0f / 3.0f;
    float q   = (a00 + a11 + a22) * third;
    float b00 = a00 - q, b11 = a11 - q, b22 = a22 - q;
    float off = fmaf(a01, a01, fmaf(a02, a02, a12 * a12));
    float p2  = fmaf(b00, b00, fmaf(b11, b11, fmaf(b22, b22, 2.0f * off)));

    float s    = p2 * (1.0f / 6.0f);
    float pinv = rsqrtf(s);            // inf when s==0; handled by clamp below
    float p    = s * pinv;             // sqrt(s); 0 when s==0 (0*inf -> NaN? no: s=0 exactly -> 0*inf=NaN, clamp path still safe)

    // det(B), B = A - q*I (symmetric)
    float detB = b00 * fmaf(b11, b22, -(a12 * a12))
               - a01 * fmaf(a01, b22, -(a12 * a02))
               + a02 * fmaf(a01, a12, -(b11 * a02));

    float pinv3 = pinv * pinv * pinv;
    float r = 0.5f * detB * pinv3;
    // clamp; also sanitizes inf/NaN from degenerate s -> r in [-1,1]
    r = fminf(fmaxf(r, -1.0f), 1.0f);
    // sanitize p too (NaN only if s==0 -> want p=0)
    p = (s > 0.0f) ? p : 0.0f;

    float phi = fast_acosf(r) * third;          // [0, pi/3]
    float two_p = 2.0f * p;
    hi  = fmaf(two_p, __cosf(phi), q);
    lo  = fmaf(two_p, __cosf(phi + 2.09439510239319549f), q);
    mid = 3.0f * q - hi - lo;
}

__global__ __launch_bounds__(256)
void eigvals3_kernel(const float* __restrict__ X, float* __restrict__ out,
                     int n, int ngroups)
{
    int g = blockIdx.x * blockDim.x + threadIdx.x;
    if (g >= ngroups) return;

    int i4 = g * 4;                   // flattened (batch, voxel) index *4
    int b0 = (i4 >= n) ? 1 : 0;       // b == 2; n divisible by 4 so no crossing
    int v  = i4 - b0 * n;

    const float* base  = X   + (unsigned)(b0 * 9) * (unsigned)n + (unsigned)v;
    float*       obase = out + (unsigned)(b0 * 3) * (unsigned)n + (unsigned)v;

    // 9 coalesced 128-bit loads (channels, stride n floats)
    float4 c0 = *(const float4*)(base + 0u * (unsigned)n);
    float4 c1 = *(const float4*)(base + 1u * (unsigned)n);
    float4 c2 = *(const float4*)(base + 2u * (unsigned)n);
    float4 c3 = *(const float4*)(base + 3u * (unsigned)n);
    float4 c4 = *(const float4*)(base + 4u * (unsigned)n);
    float4 c5 = *(const float4*)(base + 5u * (unsigned)n);
    float4 c6 = *(const float4*)(base + 6u * (unsigned)n);
    float4 c7 = *(const float4*)(base + 7u * (unsigned)n);
    float4 c8 = *(const float4*)(base + 8u * (unsigned)n);

    float4 olo, omid, ohi;

    // Symmetrize off-diagonals: a01=(c1+c3)/2, a02=(c2+c6)/2, a12=(c5+c7)/2
    {
        float a01 = 0.5f * (c1.x + c3.x), a02 = 0.5f * (c2.x + c6.x), a12 = 0.5f * (c5.x + c7.x);
        sym3eig(c0.x, a01, a02, c4.x, a12, c8.x, olo.x, omid.x, ohi.x);
    }
    {
        float a01 = 0.5f * (c1.y + c3.y), a02 = 0.5f * (c2.y + c6.y), a12 = 0.5f * (c5.y + c7.y);
        sym3eig(c0.y, a01, a02, c4.y, a12, c8.y, olo.y, omid.y, ohi.y);
    }
    {
        float a01 = 0.5f * (c1.z + c3.z), a02 = 0.5f * (c2.z + c6.z), a12 = 0.5f * (c5.z + c7.z);
        sym3eig(c0.z, a01, a02, c4.z, a12, c8.z, olo.z, omid.z, ohi.z);
    }
    {
        float a01 = 0.5f * (c1.w + c3.w), a02 = 0.5f * (c2.w + c6.w), a12 = 0.5f * (c5.w + c7.w);
        sym3eig(c0.w, a01, a02, c4.w, a12, c8.w, olo.w, omid.w, ohi.w);
    }

    // 3 coalesced 128-bit stores, ascending eigenvalue order (matches eigvalsh)
    *(float4*)(obase + 0u * (unsigned)n) = olo;
    *(float4*)(obase + 1u * (unsigned)n) = omid;
    *(float4*)(obase + 2u * (unsigned)n) = ohi;
}

extern "C" void kernel_launch(void* const* d_in, const int* in_sizes, int n_in,
                              void* d_out, int out_size)
{
    const float* X = (const float*)d_in[0];
    float* out     = (float*)d_out;

    // X: (b, 9, n); out: (b, 3, n). Problem fixes b = 2, n = 96^3.
    int n = out_size / 6;
    int total_vox = out_size / 3;     // b * n
    int ngroups = total_vox / 4;      // 4 voxels per thread (n % 4 == 0)

    int threads = 256;
    int blocks = (ngroups + threads - 1) / threads;
    eigvals3_kernel<<<blocks, threads>>>(X, out, n, ngroups);
}